// round 2
// baseline (speedup 1.0000x reference)
#include <cuda_runtime.h>
#include <math.h>

#define NB 4
#define NT 512
#define ND 1024
#define NF 4096
#define NE 8
#define NHEAD 16
#define DH 64
#define NTOK (NB*NT)          // 2048
#define CAP 2048              // per-expert slot capacity (worst case)
#define NSLOT (NE*CAP)        // 16384

// ---- static scratch (no runtime allocation allowed) ----
__device__ float g_ln[NTOK*ND];                         // 8 MB   (reused ln1 then ln2)
__device__ float g_qkv[(size_t)NTOK*3*ND];              // 25 MB
__device__ float g_scores[(size_t)NB*NHEAD*NT*NT];      // 64 MB
__device__ float g_ctx[(size_t)NTOK*ND];                // 8 MB
__device__ float g_hidden[(size_t)NSLOT*NF];            // 256 MB
__device__ int   g_slot_token[NSLOT];
__device__ float g_slot_w[NSLOT];
__device__ int   g_count[NE];

__device__ __forceinline__ float gelu_tanh(float x){
    float x3 = x*x*x;
    return 0.5f*x*(1.0f + tanhf(0.7978845608028654f*(x + 0.044715f*x3)));
}

// ---------------- LayerNorm: one block per token, D=1024 ----------------
__global__ void ln_kernel(const float* __restrict__ x,
                          const float* __restrict__ w,
                          const float* __restrict__ b,
                          float* __restrict__ y)
{
    int row = blockIdx.x;
    int t = threadIdx.x;
    const float* xr = x + (size_t)row*ND;
    float v[4];
    float s = 0.f;
    #pragma unroll
    for(int i=0;i<4;i++){ v[i] = xr[t + i*256]; s += v[i]; }
    __shared__ float red[256];
    red[t] = s; __syncthreads();
    for(int o=128;o>0;o>>=1){ if(t<o) red[t]+=red[t+o]; __syncthreads(); }
    float mu = red[0]*(1.0f/ND);
    __syncthreads();
    s = 0.f;
    #pragma unroll
    for(int i=0;i<4;i++){ float d=v[i]-mu; s += d*d; }
    red[t] = s; __syncthreads();
    for(int o=128;o>0;o>>=1){ if(t<o) red[t]+=red[t+o]; __syncthreads(); }
    float rstd = rsqrtf(red[0]*(1.0f/ND) + 1e-5f);
    float* yr = y + (size_t)row*ND;
    #pragma unroll
    for(int i=0;i<4;i++){
        int c = t + i*256;
        yr[c] = (v[i]-mu)*rstd*w[c] + b[c];
    }
}

// ---------------- Generic 128x128x8 fp32 GEMM: C = A@B + bias (+res) ----------------
__global__ __launch_bounds__(256) void gemm128_bias(
    const float* __restrict__ A, int lda,
    const float* __restrict__ Bm, int ldb,
    const float* __restrict__ bias,
    const float* __restrict__ res,
    float* __restrict__ C, int ldc, int K)
{
    __shared__ float As[8][132];
    __shared__ float Bs[8][132];
    const int tid=threadIdx.x, tx=tid&15, ty=tid>>4;
    const int m0=blockIdx.y*128, n0=blockIdx.x*128;
    const int arow=tid>>1, akq=(tid&1)*4;
    const int brow=tid>>5, bn=(tid&31)*4;
    const float* Ap = A + (size_t)(m0+arow)*lda + akq;
    const float* Bp = Bm + (size_t)brow*ldb + n0 + bn;
    float acc[8][8] = {};
    for(int k0=0;k0<K;k0+=8){
        float4 av = *(const float4*)(Ap + k0);
        float4 bv = *(const float4*)(Bp + (size_t)k0*ldb);
        As[akq+0][arow]=av.x; As[akq+1][arow]=av.y; As[akq+2][arow]=av.z; As[akq+3][arow]=av.w;
        *(float4*)&Bs[brow][bn] = bv;
        __syncthreads();
        #pragma unroll
        for(int kk=0;kk<8;kk++){
            float ra[8], rb[8];
            *(float4*)&ra[0]=*(const float4*)&As[kk][ty*8];
            *(float4*)&ra[4]=*(const float4*)&As[kk][ty*8+4];
            *(float4*)&rb[0]=*(const float4*)&Bs[kk][tx*8];
            *(float4*)&rb[4]=*(const float4*)&Bs[kk][tx*8+4];
            #pragma unroll
            for(int i=0;i<8;i++)
                #pragma unroll
                for(int j=0;j<8;j++) acc[i][j] += ra[i]*rb[j];
        }
        __syncthreads();
    }
    #pragma unroll
    for(int i=0;i<8;i++){
        int m=m0+ty*8+i;
        #pragma unroll
        for(int j=0;j<8;j++){
            int n=n0+tx*8+j;
            float v = acc[i][j] + bias[n];
            if(res) v += res[(size_t)m*ldc+n];
            C[(size_t)m*ldc+n] = v;
        }
    }
}

// ---------------- Attention scores: per (b,h)  S = Q @ K^T / 8 ----------------
__global__ __launch_bounds__(256) void attn_scores_kernel()
{
    __shared__ float As[8][132];
    __shared__ float Bs[8][132];
    const int bh = blockIdx.z;
    const int b = bh>>4, h = bh&15;
    const float* Q  = g_qkv + (size_t)b*NT*3*ND + h*DH;             // lda = 3072
    const float* Km = g_qkv + (size_t)b*NT*3*ND + ND + h*DH;        // row = token
    float* S = g_scores + (size_t)bh*NT*NT;
    const int tid=threadIdx.x, tx=tid&15, ty=tid>>4;
    const int m0=blockIdx.y*128, n0=blockIdx.x*128;
    const int arow=tid>>1, akq=(tid&1)*4;        // A: [q, d]
    const int btk=tid>>1,  bdq=(tid&1)*4;        // B^T: element [d][tk] = K[tk][d]
    const float* Ap = Q + (size_t)(m0+arow)*(3*ND) + akq;
    const float* Bp = Km + (size_t)(n0+btk)*(3*ND) + bdq;
    float acc[8][8] = {};
    for(int k0=0;k0<DH;k0+=8){
        float4 av = *(const float4*)(Ap + k0);
        float4 bv = *(const float4*)(Bp + k0);
        As[akq+0][arow]=av.x; As[akq+1][arow]=av.y; As[akq+2][arow]=av.z; As[akq+3][arow]=av.w;
        Bs[bdq+0][btk]=bv.x;  Bs[bdq+1][btk]=bv.y;  Bs[bdq+2][btk]=bv.z;  Bs[bdq+3][btk]=bv.w;
        __syncthreads();
        #pragma unroll
        for(int kk=0;kk<8;kk++){
            float ra[8], rb[8];
            *(float4*)&ra[0]=*(const float4*)&As[kk][ty*8];
            *(float4*)&ra[4]=*(const float4*)&As[kk][ty*8+4];
            *(float4*)&rb[0]=*(const float4*)&Bs[kk][tx*8];
            *(float4*)&rb[4]=*(const float4*)&Bs[kk][tx*8+4];
            #pragma unroll
            for(int i=0;i<8;i++)
                #pragma unroll
                for(int j=0;j<8;j++) acc[i][j] += ra[i]*rb[j];
        }
        __syncthreads();
    }
    #pragma unroll
    for(int i=0;i<8;i++){
        int m=m0+ty*8+i;
        #pragma unroll
        for(int j=0;j<8;j++)
            S[(size_t)m*NT + n0+tx*8+j] = acc[i][j]*0.125f;
    }
}

// ---------------- Softmax over rows of 512 (one warp per row) ----------------
__global__ void softmax_kernel()
{
    int wrow = blockIdx.x*8 + (threadIdx.x>>5);
    int lane = threadIdx.x & 31;
    float* r = g_scores + (size_t)wrow*NT;
    float v[16];
    float mx = -1e30f;
    #pragma unroll
    for(int i=0;i<16;i++){ v[i] = r[lane + 32*i]; mx = fmaxf(mx, v[i]); }
    #pragma unroll
    for(int o=16;o>0;o>>=1) mx = fmaxf(mx, __shfl_xor_sync(0xffffffffu, mx, o));
    float s = 0.f;
    #pragma unroll
    for(int i=0;i<16;i++){ v[i] = expf(v[i]-mx); s += v[i]; }
    #pragma unroll
    for(int o=16;o>0;o>>=1) s += __shfl_xor_sync(0xffffffffu, s, o);
    float inv = 1.0f/s;
    #pragma unroll
    for(int i=0;i<16;i++) r[lane + 32*i] = v[i]*inv;
}

// ---------------- ctx: per (b,h)  C = P @ V  (M=512,N=64,K=512) ----------------
__global__ __launch_bounds__(256) void attn_ctx_kernel()
{
    __shared__ float As[16][68];
    __shared__ float Bs[16][68];
    const int bh = blockIdx.z;
    const int b = bh>>4, h = bh&15;
    const float* P = g_scores + (size_t)bh*NT*NT;                      // lda = 512
    const float* V = g_qkv + (size_t)b*NT*3*ND + 2*ND + h*DH;          // ldb = 3072
    const int tid=threadIdx.x, tx=tid&15, ty=tid>>4;
    const int m0 = blockIdx.y*64;
    const int arow=tid>>2, akq=(tid&3)*4;
    const int brow=tid>>4, bn=(tid&15)*4;
    const float* Ap = P + (size_t)(m0+arow)*NT + akq;
    const float* Bp = V + (size_t)brow*(3*ND) + bn;
    float acc[4][4] = {};
    for(int k0=0;k0<NT;k0+=16){
        float4 av = *(const float4*)(Ap + k0);
        float4 bv = *(const float4*)(Bp + (size_t)k0*(3*ND));
        As[akq+0][arow]=av.x; As[akq+1][arow]=av.y; As[akq+2][arow]=av.z; As[akq+3][arow]=av.w;
        *(float4*)&Bs[brow][bn] = bv;
        __syncthreads();
        #pragma unroll
        for(int kk=0;kk<16;kk++){
            float4 a = *(const float4*)&As[kk][ty*4];
            float4 bq = *(const float4*)&Bs[kk][tx*4];
            float ra[4]={a.x,a.y,a.z,a.w}, rb[4]={bq.x,bq.y,bq.z,bq.w};
            #pragma unroll
            for(int i=0;i<4;i++)
                #pragma unroll
                for(int j=0;j<4;j++) acc[i][j] += ra[i]*rb[j];
        }
        __syncthreads();
    }
    #pragma unroll
    for(int i=0;i<4;i++){
        int q = m0 + ty*4 + i;
        #pragma unroll
        for(int j=0;j<4;j++)
            g_ctx[(size_t)(b*NT+q)*ND + h*DH + tx*4+j] = acc[i][j];
    }
}

// ---------------- MoE reset ----------------
__global__ void moe_reset_kernel()
{
    int i = blockIdx.x*256 + threadIdx.x;
    if(i < NSLOT) g_slot_token[i] = -1;
    if(i < NE) g_count[i] = 0;
}

// ---------------- Gate: softmax + top2 + scatter into expert buckets ----------------
__global__ void gate_kernel(const float* __restrict__ wg)
{
    int token = blockIdx.x*8 + (threadIdx.x>>5);
    int lane = threadIdx.x & 31;
    const float* t = g_ln + (size_t)token*ND;
    float acc[NE] = {};
    for(int d=lane; d<ND; d+=32){
        float td = t[d];
        const float* w = wg + d*NE;
        #pragma unroll
        for(int e=0;e<NE;e++) acc[e] += td*w[e];
    }
    #pragma unroll
    for(int e=0;e<NE;e++)
        #pragma unroll
        for(int o=16;o>0;o>>=1) acc[e] += __shfl_xor_sync(0xffffffffu, acc[e], o);
    if(lane==0){
        float mx = -1e30f;
        #pragma unroll
        for(int e=0;e<NE;e++) mx = fmaxf(mx, acc[e]);
        float p[NE], s=0.f;
        #pragma unroll
        for(int e=0;e<NE;e++){ p[e] = expf(acc[e]-mx); s += p[e]; }
        float inv = 1.0f/s;
        #pragma unroll
        for(int e=0;e<NE;e++) p[e] *= inv;
        int e0 = 0;
        #pragma unroll
        for(int e=1;e<NE;e++) if(p[e] > p[e0]) e0 = e;
        int e1 = (e0==0) ? 1 : 0;
        #pragma unroll
        for(int e=0;e<NE;e++) if(e!=e0 && p[e] > p[e1]) e1 = e;
        float w0 = p[e0], w1 = p[e1];
        float rn = 1.0f/(w0+w1);
        w0 *= rn; w1 *= rn;
        int p0 = atomicAdd(&g_count[e0], 1);
        g_slot_token[e0*CAP + p0] = token; g_slot_w[e0*CAP + p0] = w0;
        int p1 = atomicAdd(&g_count[e1], 1);
        g_slot_token[e1*CAP + p1] = token; g_slot_w[e1*CAP + p1] = w1;
    }
}

// ---------------- MoE GEMM1: hidden = gelu(gather(ln2) @ w1[e] + b1[e]) ----------------
__global__ __launch_bounds__(256) void moe_gemm1_kernel(
    const float* __restrict__ w1, const float* __restrict__ b1)
{
    const int e = blockIdx.y >> 4;
    const int rt = blockIdx.y & 15;
    const int cnt = g_count[e];
    if(rt*128 >= cnt) return;
    __shared__ float As[8][132];
    __shared__ float Bs[8][132];
    const int tid=threadIdx.x, tx=tid&15, ty=tid>>4;
    const int m0 = rt*128, n0 = blockIdx.x*128;
    const int arow=tid>>1, akq=(tid&1)*4;
    const int brow=tid>>5, bn=(tid&31)*4;
    const int tok = g_slot_token[e*CAP + m0 + arow];
    const bool avalid = (tok >= 0);
    const float* Ap = g_ln + (size_t)(avalid?tok:0)*ND + akq;
    const float* Bp = w1 + (size_t)e*ND*NF + (size_t)brow*NF + n0 + bn;
    float acc[8][8] = {};
    for(int k0=0;k0<ND;k0+=8){
        float4 av = avalid ? *(const float4*)(Ap + k0) : make_float4(0.f,0.f,0.f,0.f);
        float4 bv = *(const float4*)(Bp + (size_t)k0*NF);
        As[akq+0][arow]=av.x; As[akq+1][arow]=av.y; As[akq+2][arow]=av.z; As[akq+3][arow]=av.w;
        *(float4*)&Bs[brow][bn] = bv;
        __syncthreads();
        #pragma unroll
        for(int kk=0;kk<8;kk++){
            float ra[8], rb[8];
            *(float4*)&ra[0]=*(const float4*)&As[kk][ty*8];
            *(float4*)&ra[4]=*(const float4*)&As[kk][ty*8+4];
            *(float4*)&rb[0]=*(const float4*)&Bs[kk][tx*8];
            *(float4*)&rb[4]=*(const float4*)&Bs[kk][tx*8+4];
            #pragma unroll
            for(int i=0;i<8;i++)
                #pragma unroll
                for(int j=0;j<8;j++) acc[i][j] += ra[i]*rb[j];
        }
        __syncthreads();
    }
    #pragma unroll
    for(int i=0;i<8;i++){
        int sl = m0 + ty*8 + i;
        #pragma unroll
        for(int j=0;j<8;j++){
            int n = n0 + tx*8 + j;
            g_hidden[(size_t)(e*CAP+sl)*NF + n] = gelu_tanh(acc[i][j] + b1[e*NF + n]);
        }
    }
}

// ---------------- MoE GEMM2: out += w_slot * (hidden @ w2[e] + b2[e]) ----------------
__global__ __launch_bounds__(256) void moe_gemm2_kernel(
    const float* __restrict__ w2, const float* __restrict__ b2,
    float* __restrict__ out)
{
    const int e = blockIdx.y >> 4;
    const int rt = blockIdx.y & 15;
    const int cnt = g_count[e];
    if(rt*128 >= cnt) return;
    __shared__ float As[8][132];
    __shared__ float Bs[8][132];
    const int tid=threadIdx.x, tx=tid&15, ty=tid>>4;
    const int m0 = rt*128, n0 = blockIdx.x*128;
    const int arow=tid>>1, akq=(tid&1)*4;
    const int brow=tid>>5, bn=(tid&31)*4;
    const float* Ap = g_hidden + (size_t)(e*CAP + m0 + arow)*NF + akq;
    const float* Bp = w2 + (size_t)e*NF*ND + (size_t)brow*ND + n0 + bn;
    float acc[8][8] = {};
    for(int k0=0;k0<NF;k0+=8){
        float4 av = *(const float4*)(Ap + k0);
        float4 bv = *(const float4*)(Bp + (size_t)k0*ND);
        As[akq+0][arow]=av.x; As[akq+1][arow]=av.y; As[akq+2][arow]=av.z; As[akq+3][arow]=av.w;
        *(float4*)&Bs[brow][bn] = bv;
        __syncthreads();
        #pragma unroll
        for(int kk=0;kk<8;kk++){
            float ra[8], rb[8];
            *(float4*)&ra[0]=*(const float4*)&As[kk][ty*8];
            *(float4*)&ra[4]=*(const float4*)&As[kk][ty*8+4];
            *(float4*)&rb[0]=*(const float4*)&Bs[kk][tx*8];
            *(float4*)&rb[4]=*(const float4*)&Bs[kk][tx*8+4];
            #pragma unroll
            for(int i=0;i<8;i++)
                #pragma unroll
                for(int j=0;j<8;j++) acc[i][j] += ra[i]*rb[j];
        }
        __syncthreads();
    }
    #pragma unroll
    for(int i=0;i<8;i++){
        int sl = m0 + ty*8 + i;
        if(sl < cnt){
            int tok = g_slot_token[e*CAP + sl];
            float wslot = g_slot_w[e*CAP + sl];
            #pragma unroll
            for(int j=0;j<8;j++){
                int n = n0 + tx*8 + j;
                atomicAdd(&out[(size_t)tok*ND + n], wslot*(acc[i][j] + b2[e*ND + n]));
            }
        }
    }
}

// ---------------- launch ----------------
extern "C" void kernel_launch(void* const* d_in, const int* in_sizes, int n_in,
                              void* d_out, int out_size)
{
    const float* x    = (const float*)d_in[0];
    const float* ln1w = (const float*)d_in[1];
    const float* ln1b = (const float*)d_in[2];
    const float* ln2w = (const float*)d_in[3];
    const float* ln2b = (const float*)d_in[4];
    const float* wqkv = (const float*)d_in[5];
    const float* bqkv = (const float*)d_in[6];
    const float* wo   = (const float*)d_in[7];
    const float* bo   = (const float*)d_in[8];
    const float* wg   = (const float*)d_in[9];
    const float* w1   = (const float*)d_in[10];
    const float* b1   = (const float*)d_in[11];
    const float* w2   = (const float*)d_in[12];
    const float* b2   = (const float*)d_in[13];
    float* out = (float*)d_out;

    float *p_ln, *p_qkv, *p_ctx;
    cudaGetSymbolAddress((void**)&p_ln,  g_ln);
    cudaGetSymbolAddress((void**)&p_qkv, g_qkv);
    cudaGetSymbolAddress((void**)&p_ctx, g_ctx);

    // 1) ln1
    ln_kernel<<<NTOK, 256>>>(x, ln1w, ln1b, p_ln);
    // 2) qkv = ln1 @ w_qkv + b_qkv      [2048 x 3072]
    gemm128_bias<<<dim3(3*ND/128, NTOK/128), 256>>>(p_ln, ND, wqkv, 3*ND, bqkv, nullptr, p_qkv, 3*ND, ND);
    // 3) scores = QK^T / 8 per (b,h)
    attn_scores_kernel<<<dim3(NT/128, NT/128, NB*NHEAD), 256>>>();
    // 4) softmax over last dim
    softmax_kernel<<<(NB*NHEAD*NT)/8, 256>>>();
    // 5) ctx = P @ V
    attn_ctx_kernel<<<dim3(1, NT/64, NB*NHEAD), 256>>>();
    // 6) h = x + ctx @ w_o + b_o  -> d_out
    gemm128_bias<<<dim3(ND/128, NTOK/128), 256>>>(p_ctx, ND, wo, ND, bo, x, out, ND, ND);
    // 7) ln2(h)
    ln_kernel<<<NTOK, 256>>>(out, ln2w, ln2b, p_ln);
    // 8) reset routing state
    moe_reset_kernel<<<NSLOT/256, 256>>>();
    // 9) gate + top2 + scatter
    gate_kernel<<<NTOK/8, 256>>>(wg);
    // 10) expert GEMM1 + gelu
    moe_gemm1_kernel<<<dim3(NF/128, NE*16), 256>>>(w1, b1);
    // 11) expert GEMM2 + weighted atomic combine into d_out
    moe_gemm2_kernel<<<dim3(ND/128, NE*16), 256>>>(w2, b2, out);
}